// round 15
// baseline (speedup 1.0000x reference)
#include <cuda_runtime.h>
#include <cuda_fp16.h>
#include <cstdint>

#define N_TOK   2048
#define DIM     256
#define KMEM    65536
#define KSHORT  64
#define VOCAB   50257
#define RHO_C   1.0f
#define TAU_C   0.1f
#define ETA_C   0.1f

typedef unsigned long long u64;
typedef unsigned int u32;

// ---------------- scratch (static __device__ — no allocation) ----------------
__device__ __align__(16) __half g_Mh[(size_t)KMEM * DIM];     // 32 MB fp16 memory bank
__device__ __align__(16) __half g_Eh[N_TOK * DIM];
__device__ __align__(16) __half g_Yh[N_TOK * DIM];
__device__ __align__(16) u64   g_C8[(size_t)N_TOK * 4096];    // 64 MB: [t][512 strips][8 keys]
__device__ float g_E[N_TOK * DIM];
__device__ float g_X[N_TOK * DIM];
__device__ float g_Y[N_TOK * DIM];
__device__ float g_bsum[8 * DIM];
__device__ int   g_K[N_TOK * KSHORT];

#define SWZ128(o) ((o) ^ (((o) >> 3) & 0x70))
#define SMEM_BYTES 69632   // pipeline stages; reused as 128x132 fp32 stage

// ---------------- PTX helpers (all sm_80-era, safe for compute_103) ----------
__device__ __forceinline__ u32 smem_u32(const void* p) {
    u32 a;
    asm("{ .reg .u64 t; cvta.to.shared.u64 t, %1; cvt.u32.u64 %0, t; }" : "=r"(a) : "l"(p));
    return a;
}
__device__ __forceinline__ void ldsm4(u32* r, u32 addr) {
    asm volatile("ldmatrix.sync.aligned.m8n8.x4.shared.b16 {%0,%1,%2,%3}, [%4];"
        : "=r"(r[0]), "=r"(r[1]), "=r"(r[2]), "=r"(r[3]) : "r"(addr));
}
__device__ __forceinline__ void mma_f16(float* c, const u32* a, u32 b0, u32 b1) {
    asm volatile("mma.sync.aligned.m16n8k16.row.col.f32.f16.f16.f32 "
        "{%0,%1,%2,%3}, {%4,%5,%6,%7}, {%8,%9}, {%0,%1,%2,%3};"
        : "+f"(c[0]), "+f"(c[1]), "+f"(c[2]), "+f"(c[3])
        : "r"(a[0]), "r"(a[1]), "r"(a[2]), "r"(a[3]), "r"(b0), "r"(b1));
}
__device__ __forceinline__ void cp16(u32 dst, const void* src) {
    asm volatile("cp.async.cg.shared.global [%0], [%1], 16;" :: "r"(dst), "l"(src));
}
__device__ __forceinline__ void cp_commit() { asm volatile("cp.async.commit_group;"); }
template <int N>
__device__ __forceinline__ void cp_wait() { asm volatile("cp.async.wait_group %0;" :: "n"(N)); }

__device__ __forceinline__ u32 ordf(float f) {
    u32 u = __float_as_uint(f);
    return (u & 0x80000000u) ? ~u : (u | 0x80000000u);
}
__device__ __forceinline__ u64 mk_key(float v, int idx) {
    return ((u64)ordf(v) << 32) | (u32)(65535 - idx);
}

// ---------------- embed gather (fp32 + fp16 copies) ----------------
__global__ void k_embed(const int* __restrict__ tok, const float* __restrict__ tab,
                        float* __restrict__ E, __half* __restrict__ Eh) {
    int t = blockIdx.x, c = threadIdx.x;
    float v = tab[(size_t)tok[t] * DIM + c];
    E[t * DIM + c] = v;
    Eh[t * DIM + c] = __float2half(v);
}

// ---------------- fp32 -> fp16 bulk convert ----------------
__global__ void k_cvt_h(const float* __restrict__ src, __half* __restrict__ dst, int n4) {
    int i = blockIdx.x * 256 + threadIdx.x;
    if (i < n4) {
        float4 v = ((const float4*)src)[i];
        ((__half2*)dst)[2 * i]     = __floats2half2_rn(v.x, v.y);
        ((__half2*)dst)[2 * i + 1] = __floats2half2_rn(v.z, v.w);
    }
}

// ---------------- causal cumulative mean (2-phase) ----------------
__global__ void k_colsum(const float* __restrict__ E, float* __restrict__ bs) {
    int b = blockIdx.x, j = threadIdx.x;
    float s = 0.f;
    int base = b * 256;
#pragma unroll 4
    for (int r = 0; r < 256; r++) s += E[(base + r) * DIM + j];
    bs[b * DIM + j] = s;
}

__global__ void k_cummean(const float* __restrict__ E, const float* __restrict__ bs,
                          float* __restrict__ X) {
    int b = blockIdx.x, j = threadIdx.x;
    float acc = 0.f;
    for (int p = 0; p < b; p++) acc += bs[p * DIM + j];
    int base = b * 256;
    for (int r = 0; r < 256; r++) {
        int t = base + r;
        acc += E[t * DIM + j];
        X[t * DIM + j] = acc / (float)(t + 1);
    }
}

// ---------------- fp16 HMMA GEMM, cp.async double-buffered ----------------
// C[row][col] = dot_256(A[row], B[col]); 128x128 CTA tile, K=256 (4 chunks).
// OUTF32=0: scores -> per-token top-8 strip keys into C8 (no score array!).
// OUTF32=1: fp32 out, col guard (logits), smem-staged coalesced stores.
template <int OUTF32>
__global__ __launch_bounds__(256, 2) void k_hmma(
    const __half* __restrict__ A,
    const __half* __restrict__ B,
    u64* __restrict__ C8,
    float* __restrict__ Fout,
    int ncols)
{
    extern __shared__ char smem[];
    u32 aAddr[2] = { smem_u32(smem),         smem_u32(smem + 16384) };
    u32 bAddr[2] = { smem_u32(smem + 32768), smem_u32(smem + 49152) };
    int tid = threadIdx.x;
    int w = tid >> 5, l = tid & 31;
    int wm = w & 3, wn = w >> 2;
    int rowBase = blockIdx.y * 128;
    int colBase = blockIdx.x * 128;

    float acc[2][8][4];
#pragma unroll
    for (int mi = 0; mi < 2; mi++)
#pragma unroll
        for (int ni = 0; ni < 8; ni++)
#pragma unroll
            for (int q = 0; q < 4; q++) acc[mi][ni][q] = 0.f;

    int a_row = wm * 32 + (l & 7) + ((l >> 3) & 1) * 8;   // + mi*16
    int a_kb  = ((l >> 4) * 8) * 2;                        // + ks*32
    int b_row = wn * 64 + (l & 7) + (l >> 4) * 8;          // + nj*16
    int b_kb  = (((l >> 3) & 1) * 8) * 2;                  // + ks*32

    // prologue: async-load chunk 0 into stage 0
#pragma unroll
    for (int g = tid; g < 1024; g += 256) {
        int row = g >> 3, seg = g & 7;
        cp16(aAddr[0] + SWZ128(row * 128 + seg * 16),
             A + (size_t)(rowBase + row) * DIM + seg * 8);
    }
#pragma unroll
    for (int g = tid; g < 1024; g += 256) {
        int row = g >> 3, seg = g & 7;
        cp16(bAddr[0] + SWZ128(row * 128 + seg * 16),
             B + (size_t)(colBase + row) * DIM + seg * 8);
    }
    cp_commit();

#pragma unroll
    for (int i = 0; i < 4; i++) {
        int s = i & 1;
        if (i + 1 < 4) {
            int kc = (i + 1) << 6, sn = (i + 1) & 1;
#pragma unroll
            for (int g = tid; g < 1024; g += 256) {
                int row = g >> 3, seg = g & 7;
                cp16(aAddr[sn] + SWZ128(row * 128 + seg * 16),
                     A + (size_t)(rowBase + row) * DIM + kc + seg * 8);
            }
#pragma unroll
            for (int g = tid; g < 1024; g += 256) {
                int row = g >> 3, seg = g & 7;
                cp16(bAddr[sn] + SWZ128(row * 128 + seg * 16),
                     B + (size_t)(colBase + row) * DIM + kc + seg * 8);
            }
            cp_commit();
            cp_wait<1>();
        } else {
            cp_wait<0>();
        }
        __syncthreads();
#pragma unroll
        for (int ks = 0; ks < 4; ks++) {
            u32 a[2][4];
#pragma unroll
            for (int mi = 0; mi < 2; mi++)
                ldsm4(a[mi], aAddr[s] + SWZ128((a_row + mi * 16) * 128 + a_kb + ks * 32));
            u32 b[4][4];
#pragma unroll
            for (int nj = 0; nj < 4; nj++)
                ldsm4(b[nj], bAddr[s] + SWZ128((b_row + nj * 16) * 128 + b_kb + ks * 32));
#pragma unroll
            for (int mi = 0; mi < 2; mi++)
#pragma unroll
                for (int nj = 0; nj < 4; nj++) {
                    mma_f16(acc[mi][nj * 2],     a[mi], b[nj][0], b[nj][1]);
                    mma_f16(acc[mi][nj * 2 + 1], a[mi], b[nj][2], b[nj][3]);
                }
        }
        __syncthreads();
    }

    // ---- epilogue: stage 128x132 fp32 tile in smem ----
    float* st = (float*)smem;                 // 128*132*4 = 67584 B
#pragma unroll
    for (int mi = 0; mi < 2; mi++) {
        int rl0 = wm * 32 + mi * 16 + (l >> 2);
#pragma unroll
        for (int ni = 0; ni < 8; ni++) {
            int cl = wn * 64 + ni * 8 + (l & 3) * 2;
            st[rl0 * 132 + cl]           = acc[mi][ni][0];
            st[rl0 * 132 + cl + 1]       = acc[mi][ni][1];
            st[(rl0 + 8) * 132 + cl]     = acc[mi][ni][2];
            st[(rl0 + 8) * 132 + cl + 1] = acc[mi][ni][3];
        }
    }
    __syncthreads();

    if (OUTF32) {
        for (int g = tid; g < 16384; g += 256) {
            int row = g >> 7, col = g & 127;
            int c = colBase + col;
            if (c < ncols)
                Fout[(size_t)(rowBase + row) * ncols + c] = st[row * 132 + col];
        }
    } else {
        // per-token top-8 of this 128-slot strip.
        // 2 lanes per row (adjacent lanes, same warp): halves 0/1 of 64 cols.
        int row = tid >> 1, half = tid & 1;
        u64 top[8];
#pragma unroll
        for (int i = 0; i < 8; i++) top[i] = 0ull;
        const float* sr = &st[row * 132 + half * 64];
#pragma unroll 8
        for (int c = 0; c < 64; c++) {
            u64 key = mk_key(sr[c], colBase + half * 64 + c);
            if (key > top[7]) {
                top[7] = key;
#pragma unroll
                for (int j = 7; j > 0; j--) {
                    if (top[j] > top[j - 1]) { u64 tmp = top[j]; top[j] = top[j - 1]; top[j - 1] = tmp; }
                }
            }
        }
        // merge partner lane's top-8 (lane^1): SNAPSHOT FIRST, then insert.
        // (R14 bug: shuffling from a list being mutated by the partner.)
        u64 other[8];
#pragma unroll
        for (int i = 0; i < 8; i++)
            other[i] = __shfl_xor_sync(0xffffffffu, top[i], 1);
#pragma unroll
        for (int i = 0; i < 8; i++) {
            u64 pk = other[i];
            if (pk > top[7]) {
                top[7] = pk;
#pragma unroll
                for (int j = 7; j > 0; j--) {
                    if (top[j] > top[j - 1]) { u64 tmp = top[j]; top[j] = top[j - 1]; top[j - 1] = tmp; }
                }
            }
        }
        if (half == 0) {
            u64* dst = &C8[(size_t)(rowBase + row) * 4096 + blockIdx.x * 8];
#pragma unroll
            for (int i = 0; i < 8; i++) dst[i] = top[i];
        }
    }
}

// ---------------- top-k from C8: tau -> collect -> exact rescore -> top-64 ---
__global__ __launch_bounds__(256) void k_topk_rescore(
    const u64* __restrict__ C8,
    const float* __restrict__ E,
    const float* __restrict__ Mm,
    int* __restrict__ Kset
) {
    __shared__ u64 cand[2048];
    __shared__ u64 smax[512];
    __shared__ u64 tmax[256];
    __shared__ float Erow[256];
    __shared__ int cslot[128];
    __shared__ int cnt;
    int tid = threadIdx.x;
    int t = blockIdx.x;
    const u64* row = C8 + (size_t)t * 4096;
    Erow[tid] = E[t * DIM + tid];
    if (tid == 0) cnt = 0;

    // tau: 128th-largest of the 512 strip maxima (lead key of each strip)
    smax[tid]       = row[tid * 8];
    smax[tid + 256] = row[(tid + 256) * 8];
    __syncthreads();
    for (int k = 2; k <= 512; k <<= 1) {
        for (int j = k >> 1; j > 0; j >>= 1) {
            for (int e = tid; e < 512; e += 256) {
                int ix = e ^ j;
                if (ix > e) {
                    u64 a = smax[e], b = smax[ix];
                    bool up = ((e & k) == 0);
                    if (up ? (a < b) : (a > b)) { smax[e] = b; smax[ix] = a; }
                }
            }
            __syncthreads();
        }
    }
    u64 tau = smax[127];   // >=128 keys >= tau exist among the strip leads
    __syncthreads();

    // collect all stored keys >= tau (4096 keys, coalesced)
#pragma unroll
    for (int i = 0; i < 16; i++) {
        u64 key = row[tid + i * 256];
        if (key >= tau) {
            int p = atomicAdd(&cnt, 1);
            if (p < 2048) cand[p] = key;
        }
    }
    __syncthreads();
    int c = cnt; if (c > 2048) c = 2048;
    for (int e = c + tid; e < 2048; e += 256) cand[e] = 0ull;
    __syncthreads();
    for (int k = 2; k <= 2048; k <<= 1) {
        for (int j = k >> 1; j > 0; j >>= 1) {
            for (int e = tid; e < 2048; e += 256) {
                int ix = e ^ j;
                if (ix > e) {
                    u64 a = cand[e], b = cand[ix];
                    bool up = ((e & k) == 0);
                    if (up ? (a < b) : (a > b)) { cand[e] = b; cand[ix] = a; }
                }
            }
            __syncthreads();
        }
    }
    if (tid < 128) cslot[tid] = 65535 - (int)(cand[tid] & 0xFFFFull);
    __syncthreads();

    // exact fp32 rescore of 128 candidates (true top-64 provably inside:
    // fp16 approx sigma ~1.6e-5 vs top64->128 margin ~1.9e-3)
    {
        int w = tid >> 5, l = tid & 31;
        for (int j = 0; j < 16; j++) {
            int ci = w * 16 + j;
            int slot = cslot[ci];
            const float* mrow = &Mm[(size_t)slot * DIM];
            float p = 0.f;
#pragma unroll
            for (int i = 0; i < 8; i++) p = fmaf(Erow[l + 32 * i], mrow[l + 32 * i], p);
#pragma unroll
            for (int o = 16; o > 0; o >>= 1) p += __shfl_xor_sync(0xffffffffu, p, o);
            if (l == 0) tmax[ci] = mk_key(p, slot);
        }
    }
    if (tid >= 128) tmax[tid] = 0ull;
    __syncthreads();

    for (int k = 2; k <= 256; k <<= 1) {
        for (int j = k >> 1; j > 0; j >>= 1) {
            int ix = tid ^ j;
            if (ix > tid) {
                u64 a = tmax[tid], b = tmax[ix];
                bool up = ((tid & k) == 0);
                if (up ? (a < b) : (a > b)) { tmax[tid] = b; tmax[ix] = a; }
            }
            __syncthreads();
        }
    }
    if (tid < 64) Kset[t * 64 + tid] = 65535 - (int)(tmax[tid] & 0xFFFFull);
}

// ---------------- solver: 4 ADMM/mirror-descent steps per token ----------------
#define SLV_FLOATS (64 * 257 + 256 * 17 + 256 + 256 + 64 + 64 + 4 * 64 + 2 + 64)
#define SLV_BYTES  (SLV_FLOATS * 4)

__global__ __launch_bounds__(256) void k_solver(const float* __restrict__ X,
                                                const float* __restrict__ M,
                                                const float* __restrict__ A,
                                                const int* __restrict__ Kidx,
                                                float* __restrict__ Yout,
                                                __half* __restrict__ Yh) {
    extern __shared__ float sm[];
    float* Mg   = sm;                 // [64][257]
    float* band = Mg + 64 * 257;      // [256][17]
    float* Ysm  = band + 256 * 17;    // [256]
    float* vsm  = Ysm + 256;          // [256]
    float* Psm  = vsm + 256;          // [64]
    float* Lsm  = Psm + 64;           // [64]
    float* gp   = Lsm + 64;           // [4][64]
    float* red  = gp + 256;           // [2]
    int*   sidx = (int*)(red + 2);    // [64]

    int tid = threadIdx.x;
    int t = blockIdx.x;
    if (tid < 64) sidx[tid] = Kidx[t * 64 + tid];
    __syncthreads();
    for (int r = 0; r < 64; r++)
        Mg[r * 257 + tid] = M[(size_t)sidx[r] * DIM + tid];
    {
        int j = tid;
#pragma unroll
        for (int o = 0; o < 17; o++) {
            int i = j - 8 + o;
            band[j * 17 + o] = (i >= 0 && i < 256) ? A[j * 256 + i] : 0.f;
        }
    }
    float xr = X[t * DIM + tid];
    if (tid < 64) Psm[tid] = 1.0f / 64.0f;
    __syncthreads();
    {
        float y0 = 0.f;
        for (int k = 0; k < 64; k++) y0 = fmaf(Psm[k], Mg[k * 257 + tid], y0);
        Ysm[tid] = y0;
    }
    float lam = 0.f;
    __syncthreads();

    for (int step = 0; step < 4; step++) {
        float ymp = 0.f;
#pragma unroll 8
        for (int k = 0; k < 64; k++) ymp = fmaf(Psm[k], Mg[k * 257 + tid], ymp);
        float yold = Ysm[tid];
        float r_ = yold - ymp;
        lam = fmaf(RHO_C, r_, lam);
        float yab = 0.f;
#pragma unroll
        for (int o = 0; o < 17; o++) {
            int i = tid - 8 + o;
            if (i >= 0 && i < 256) yab = fmaf(band[tid * 17 + o], Ysm[i], yab);
        }
        float gY = yab - xr + lam + RHO_C * r_;
        float ynew = yold - TAU_C * gY;
        __syncthreads();
        Ysm[tid] = ynew;
        vsm[tid] = RHO_C * (ynew - ymp) + lam;
        __syncthreads();
        {
            int k = tid & 63, part = tid >> 6;
            const float* vv = vsm + part * 64;
            const float* mm = Mg + k * 257 + part * 64;
            float p_ = 0.f;
#pragma unroll 8
            for (int jj = 0; jj < 64; jj++) p_ = fmaf(vv[jj], mm[jj], p_);
            gp[part * 64 + k] = p_;
        }
        __syncthreads();
        if (tid < 64) {
            float gPk = -(gp[tid] + gp[64 + tid] + gp[128 + tid] + gp[192 + tid]);
            Lsm[tid] = logf(Psm[tid] + 1e-20f) - ETA_C * gPk;
        }
        __syncthreads();
        if (tid < 32) {
            float m_ = fmaxf(Lsm[tid], Lsm[tid + 32]);
            for (int o = 16; o > 0; o >>= 1) m_ = fmaxf(m_, __shfl_xor_sync(0xffffffffu, m_, o));
            if (tid == 0) red[0] = m_;
        }
        __syncthreads();
        if (tid < 64) Psm[tid] = expf(Lsm[tid] - red[0]);
        __syncthreads();
        if (tid < 32) {
            float s_ = Psm[tid] + Psm[tid + 32];
            for (int o = 16; o > 0; o >>= 1) s_ += __shfl_xor_sync(0xffffffffu, s_, o);
            if (tid == 0) red[1] = s_;
        }
        __syncthreads();
        if (tid < 64) Psm[tid] = Psm[tid] / red[1];
        __syncthreads();
    }
    float yfin = Ysm[tid];
    Yout[t * DIM + tid] = yfin;
    Yh[t * DIM + tid] = __float2half(yfin);
}

// ---------------- launcher ----------------
extern "C" void kernel_launch(void* const* d_in, const int* in_sizes, int n_in,
                              void* d_out, int out_size) {
    const int*   tokens = (const int*)d_in[0];
    const float* tab    = (const float*)d_in[1];
    const float* M      = (const float*)d_in[2];
    const float* A      = (const float*)d_in[3];
    float* out = (float*)d_out;

    __half *pMh, *pEh, *pYh;
    u64* pC8;
    float *pE, *pX, *pY, *pB; int* pK;
    cudaGetSymbolAddress((void**)&pMh, g_Mh);
    cudaGetSymbolAddress((void**)&pEh, g_Eh);
    cudaGetSymbolAddress((void**)&pYh, g_Yh);
    cudaGetSymbolAddress((void**)&pC8, g_C8);
    cudaGetSymbolAddress((void**)&pE, g_E);
    cudaGetSymbolAddress((void**)&pX, g_X);
    cudaGetSymbolAddress((void**)&pY, g_Y);
    cudaGetSymbolAddress((void**)&pB, g_bsum);
    cudaGetSymbolAddress((void**)&pK, g_K);

    k_embed<<<N_TOK, 256>>>(tokens, tab, pE, pEh);
    k_colsum<<<8, 256>>>(pE, pB);
    k_cummean<<<8, 256>>>(pE, pB, pX);
    k_cvt_h<<<(KMEM * DIM / 4 + 255) / 256, 256>>>(M, pMh, KMEM * DIM / 4);

    cudaFuncSetAttribute(k_hmma<0>, cudaFuncAttributeMaxDynamicSharedMemorySize, SMEM_BYTES);
    cudaFuncSetAttribute(k_hmma<1>, cudaFuncAttributeMaxDynamicSharedMemorySize, SMEM_BYTES);

    // scores: fp16 HMMA -> per-strip top-8 keys only (no 256MB score array)
    dim3 gs(KMEM / 128, N_TOK / 128);
    k_hmma<0><<<gs, 256, SMEM_BYTES>>>(pEh, pMh, pC8, nullptr, KMEM);

    // tau -> collect from C8 -> exact fp32 rescore -> exact top-64
    k_topk_rescore<<<N_TOK, 256>>>(pC8, pE, M, pK);

    cudaFuncSetAttribute(k_solver, cudaFuncAttributeMaxDynamicSharedMemorySize, SLV_BYTES);
    k_solver<<<N_TOK, 256, SLV_BYTES>>>(pX, M, A, pK, pY, pYh);

    // logits: single fp16 HMMA (error ~2.9e-4 << 1e-3), staged coalesced stores
    dim3 gl((VOCAB + 127) / 128, N_TOK / 128);
    k_hmma<1><<<gl, 256, SMEM_BYTES>>>(pYh, pMh, nullptr, out, VOCAB);
}

// round 16
// speedup vs baseline: 1.2650x; 1.2650x over previous
#include <cuda_runtime.h>
#include <cuda_fp16.h>
#include <cstdint>

#define N_TOK   2048
#define DIM     256
#define KMEM    65536
#define KSHORT  64
#define VOCAB   50257
#define RHO_C   1.0f
#define TAU_C   0.1f
#define ETA_C   0.1f

typedef unsigned long long u64;
typedef unsigned int u32;

// ---------------- scratch (static __device__ — no allocation) ----------------
__device__ __align__(16) __half g_Sh[(size_t)N_TOK * KMEM];   // 256 MB approx scores
__device__ __align__(16) __half g_Mh[(size_t)KMEM * DIM];     // 32 MB fp16 memory bank
__device__ __align__(16) __half g_Eh[N_TOK * DIM];
__device__ __align__(16) __half g_Yh[N_TOK * DIM];
__device__ u64   g_Gmax[(size_t)N_TOK * 512];                 // 8 MB strip maxima
__device__ float g_E[N_TOK * DIM];
__device__ float g_X[N_TOK * DIM];
__device__ float g_Y[N_TOK * DIM];
__device__ float g_bsum[8 * DIM];
__device__ int   g_K[N_TOK * KSHORT];

#define SWZ128(o) ((o) ^ (((o) >> 3) & 0x70))
#define SMEM_BYTES 69632   // 64KB pipeline stages, reused as 128x132 fp32 stage + rowmax

// ---------------- PTX helpers (all sm_80-era, safe for compute_103) ----------
__device__ __forceinline__ u32 smem_u32(const void* p) {
    u32 a;
    asm("{ .reg .u64 t; cvta.to.shared.u64 t, %1; cvt.u32.u64 %0, t; }" : "=r"(a) : "l"(p));
    return a;
}
__device__ __forceinline__ void ldsm4(u32* r, u32 addr) {
    asm volatile("ldmatrix.sync.aligned.m8n8.x4.shared.b16 {%0,%1,%2,%3}, [%4];"
        : "=r"(r[0]), "=r"(r[1]), "=r"(r[2]), "=r"(r[3]) : "r"(addr));
}
__device__ __forceinline__ void mma_f16(float* c, const u32* a, u32 b0, u32 b1) {
    asm volatile("mma.sync.aligned.m16n8k16.row.col.f32.f16.f16.f32 "
        "{%0,%1,%2,%3}, {%4,%5,%6,%7}, {%8,%9}, {%0,%1,%2,%3};"
        : "+f"(c[0]), "+f"(c[1]), "+f"(c[2]), "+f"(c[3])
        : "r"(a[0]), "r"(a[1]), "r"(a[2]), "r"(a[3]), "r"(b0), "r"(b1));
}
__device__ __forceinline__ void cp16(u32 dst, const void* src) {
    asm volatile("cp.async.cg.shared.global [%0], [%1], 16;" :: "r"(dst), "l"(src));
}
__device__ __forceinline__ void cp_commit() { asm volatile("cp.async.commit_group;"); }
template <int N>
__device__ __forceinline__ void cp_wait() { asm volatile("cp.async.wait_group %0;" :: "n"(N)); }

__device__ __forceinline__ u32 ordf(float f) {
    u32 u = __float_as_uint(f);
    return (u & 0x80000000u) ? ~u : (u | 0x80000000u);
}
__device__ __forceinline__ u64 mk_key(float v, int idx) {
    return ((u64)ordf(v) << 32) | (u32)(65535 - idx);
}

// ---------------- embed gather (fp32 + fp16 copies) ----------------
__global__ void k_embed(const int* __restrict__ tok, const float* __restrict__ tab,
                        float* __restrict__ E, __half* __restrict__ Eh) {
    int t = blockIdx.x, c = threadIdx.x;
    float v = tab[(size_t)tok[t] * DIM + c];
    E[t * DIM + c] = v;
    Eh[t * DIM + c] = __float2half(v);
}

// ---------------- fp32 -> fp16 bulk convert ----------------
__global__ void k_cvt_h(const float* __restrict__ src, __half* __restrict__ dst, int n4) {
    int i = blockIdx.x * 256 + threadIdx.x;
    if (i < n4) {
        float4 v = ((const float4*)src)[i];
        ((__half2*)dst)[2 * i]     = __floats2half2_rn(v.x, v.y);
        ((__half2*)dst)[2 * i + 1] = __floats2half2_rn(v.z, v.w);
    }
}

// ---------------- causal cumulative mean (2-phase) ----------------
__global__ void k_colsum(const float* __restrict__ E, float* __restrict__ bs) {
    int b = blockIdx.x, j = threadIdx.x;
    float s = 0.f;
    int base = b * 256;
#pragma unroll 4
    for (int r = 0; r < 256; r++) s += E[(base + r) * DIM + j];
    bs[b * DIM + j] = s;
}

__global__ void k_cummean(const float* __restrict__ E, const float* __restrict__ bs,
                          float* __restrict__ X) {
    int b = blockIdx.x, j = threadIdx.x;
    float acc = 0.f;
    for (int p = 0; p < b; p++) acc += bs[p * DIM + j];
    int base = b * 256;
    for (int r = 0; r < 256; r++) {
        int t = base + r;
        acc += E[t * DIM + j];
        X[t * DIM + j] = acc / (float)(t + 1);
    }
}

// ---------------- fp16 HMMA GEMM, cp.async double-buffered ----------------
// C[row][col] = dot_256(A[row], B[col]); 128x128 CTA tile, K=256 (4 chunks).
// GRID: blockIdx.x = ROW (token) block — fastest-varying — so the 16 CTAs
// sharing one B (M) tile are co-resident and B is served from L2 after a
// single DRAM read (M re-read 16x -> 1x). blockIdx.y = COL block.
// OUTF32=0: half out + per-CTA strip-max keys -> Gmax (scores).
// OUTF32=1: fp32 out, col guard (logits).
template <int OUTF32>
__global__ __launch_bounds__(256, 2) void k_hmma(
    const __half* __restrict__ A,
    const __half* __restrict__ B,
    __half* __restrict__ Sout,
    float* __restrict__ Fout,
    u64* __restrict__ Gmax,
    int ncols)
{
    extern __shared__ char smem[];
    u32 aAddr[2] = { smem_u32(smem),         smem_u32(smem + 16384) };
    u32 bAddr[2] = { smem_u32(smem + 32768), smem_u32(smem + 49152) };
    int tid = threadIdx.x;
    int w = tid >> 5, l = tid & 31;
    int wm = w & 3, wn = w >> 2;
    int rowBase = blockIdx.x * 128;    // token block (fastest-varying)
    int colBase = blockIdx.y * 128;    // slot/vocab block

    float acc[2][8][4];
#pragma unroll
    for (int mi = 0; mi < 2; mi++)
#pragma unroll
        for (int ni = 0; ni < 8; ni++)
#pragma unroll
            for (int q = 0; q < 4; q++) acc[mi][ni][q] = 0.f;

    int a_row = wm * 32 + (l & 7) + ((l >> 3) & 1) * 8;   // + mi*16
    int a_kb  = ((l >> 4) * 8) * 2;                        // + ks*32
    int b_row = wn * 64 + (l & 7) + (l >> 4) * 8;          // + nj*16
    int b_kb  = (((l >> 3) & 1) * 8) * 2;                  // + ks*32

    // prologue: async-load chunk 0 into stage 0
#pragma unroll
    for (int g = tid; g < 1024; g += 256) {
        int row = g >> 3, seg = g & 7;
        cp16(aAddr[0] + SWZ128(row * 128 + seg * 16),
             A + (size_t)(rowBase + row) * DIM + seg * 8);
    }
#pragma unroll
    for (int g = tid; g < 1024; g += 256) {
        int row = g >> 3, seg = g & 7;
        cp16(bAddr[0] + SWZ128(row * 128 + seg * 16),
             B + (size_t)(colBase + row) * DIM + seg * 8);
    }
    cp_commit();

#pragma unroll
    for (int i = 0; i < 4; i++) {
        int s = i & 1;
        if (i + 1 < 4) {
            int kc = (i + 1) << 6, sn = (i + 1) & 1;
#pragma unroll
            for (int g = tid; g < 1024; g += 256) {
                int row = g >> 3, seg = g & 7;
                cp16(aAddr[sn] + SWZ128(row * 128 + seg * 16),
                     A + (size_t)(rowBase + row) * DIM + kc + seg * 8);
            }
#pragma unroll
            for (int g = tid; g < 1024; g += 256) {
                int row = g >> 3, seg = g & 7;
                cp16(bAddr[sn] + SWZ128(row * 128 + seg * 16),
                     B + (size_t)(colBase + row) * DIM + kc + seg * 8);
            }
            cp_commit();
            cp_wait<1>();
        } else {
            cp_wait<0>();
        }
        __syncthreads();
#pragma unroll
        for (int ks = 0; ks < 4; ks++) {
            u32 a[2][4];
#pragma unroll
            for (int mi = 0; mi < 2; mi++)
                ldsm4(a[mi], aAddr[s] + SWZ128((a_row + mi * 16) * 128 + a_kb + ks * 32));
            u32 b[4][4];
#pragma unroll
            for (int nj = 0; nj < 4; nj++)
                ldsm4(b[nj], bAddr[s] + SWZ128((b_row + nj * 16) * 128 + b_kb + ks * 32));
#pragma unroll
            for (int mi = 0; mi < 2; mi++)
#pragma unroll
                for (int nj = 0; nj < 4; nj++) {
                    mma_f16(acc[mi][nj * 2],     a[mi], b[nj][0], b[nj][1]);
                    mma_f16(acc[mi][nj * 2 + 1], a[mi], b[nj][2], b[nj][3]);
                }
        }
        __syncthreads();
    }

    // ---- epilogue: stage 128x132 fp32 tile in smem, then coalesced copy-out --
    float* st = (float*)smem;                 // 128*132*4 = 67584 B
    u64* rowmax = (u64*)(smem + 67584);       // 128*8 = 1024 B
    if (!OUTF32 && tid < 128) rowmax[tid] = 0ull;
    __syncthreads();

#pragma unroll
    for (int mi = 0; mi < 2; mi++) {
        int rl0 = wm * 32 + mi * 16 + (l >> 2);
        u64 km0 = 0ull, km8 = 0ull;
#pragma unroll
        for (int ni = 0; ni < 8; ni++) {
            int cl = wn * 64 + ni * 8 + (l & 3) * 2;
            st[rl0 * 132 + cl]           = acc[mi][ni][0];
            st[rl0 * 132 + cl + 1]       = acc[mi][ni][1];
            st[(rl0 + 8) * 132 + cl]     = acc[mi][ni][2];
            st[(rl0 + 8) * 132 + cl + 1] = acc[mi][ni][3];
            if (!OUTF32) {
                // keys from half-rounded values: consistent with stored scores
                int sl = colBase + cl;
                u64 k0 = mk_key(__half2float(__float2half(acc[mi][ni][0])), sl);
                u64 k1 = mk_key(__half2float(__float2half(acc[mi][ni][1])), sl + 1);
                u64 k2 = mk_key(__half2float(__float2half(acc[mi][ni][2])), sl);
                u64 k3 = mk_key(__half2float(__float2half(acc[mi][ni][3])), sl + 1);
                if (k1 > k0) k0 = k1;
                if (k3 > k2) k2 = k3;
                if (k0 > km0) km0 = k0;
                if (k2 > km8) km8 = k2;
            }
        }
        if (!OUTF32) {
            atomicMax(&rowmax[rl0], km0);
            atomicMax(&rowmax[rl0 + 8], km8);
        }
    }
    __syncthreads();

    if (OUTF32) {
        for (int g = tid; g < 16384; g += 256) {
            int row = g >> 7, col = g & 127;
            int c = colBase + col;
            if (c < ncols)
                Fout[(size_t)(rowBase + row) * ncols + c] = st[row * 132 + col];
        }
    } else {
        for (int g = tid; g < 8192; g += 256) {
            int row = g >> 6, cp = g & 63;
            float v0 = st[row * 132 + cp * 2];
            float v1 = st[row * 132 + cp * 2 + 1];
            *(__half2*)&Sout[(size_t)(rowBase + row) * (size_t)ncols + colBase + cp * 2] =
                __floats2half2_rn(v0, v1);
        }
        if (tid < 128)
            Gmax[(size_t)(rowBase + tid) * 512 + blockIdx.y] = rowmax[tid];
    }
}

// ---------------- top-k: Gmax tau -> collect -> exact rescore -> top-64 ------
__global__ __launch_bounds__(256) void k_topk_rescore(
    const __half* __restrict__ S,
    const u64* __restrict__ Gmax,
    const float* __restrict__ E,
    const float* __restrict__ Mm,
    int* __restrict__ Kset
) {
    __shared__ u64 cand[2048];
    __shared__ u64 smax[512];
    __shared__ u64 tmax[256];
    __shared__ float Erow[256];
    __shared__ int cslot[128];
    __shared__ int cnt;
    int tid = threadIdx.x;
    int t = blockIdx.x;
    Erow[tid] = E[t * DIM + tid];
    if (tid == 0) cnt = 0;

    // tau from precomputed 512 strip maxima (each over 128 slots)
    smax[tid]       = Gmax[(size_t)t * 512 + tid];
    smax[tid + 256] = Gmax[(size_t)t * 512 + tid + 256];
    __syncthreads();
    for (int k = 2; k <= 512; k <<= 1) {
        for (int j = k >> 1; j > 0; j >>= 1) {
            for (int e = tid; e < 512; e += 256) {
                int ix = e ^ j;
                if (ix > e) {
                    u64 a = smax[e], b = smax[ix];
                    bool up = ((e & k) == 0);
                    if (up ? (a < b) : (a > b)) { smax[e] = b; smax[ix] = a; }
                }
            }
            __syncthreads();
        }
    }
    u64 tau = smax[127];   // >=128 keys >= tau -> approx top-128 is a subset
    __syncthreads();

    // collection pass: uint4 = 8 halves per load, coalesced
    {
        const uint4* row4 = (const uint4*)(S + (size_t)t * KMEM);
#pragma unroll 4
        for (int i = 0; i < 32; i++) {
            int j4 = tid + (i << 8);
            uint4 v = row4[j4];
            int base = j4 * 8;
            u32 words[4] = { v.x, v.y, v.z, v.w };
#pragma unroll
            for (int q = 0; q < 4; q++) {
                __half2 h = *(__half2*)&words[q];
                u64 k0 = mk_key(__low2float(h), base + 2 * q);
                u64 k1 = mk_key(__high2float(h), base + 2 * q + 1);
                if (k0 >= tau) { int p = atomicAdd(&cnt, 1); if (p < 2048) cand[p] = k0; }
                if (k1 >= tau) { int p = atomicAdd(&cnt, 1); if (p < 2048) cand[p] = k1; }
            }
        }
    }
    __syncthreads();
    int c = cnt; if (c > 2048) c = 2048;
    for (int e = c + tid; e < 2048; e += 256) cand[e] = 0ull;
    __syncthreads();
    for (int k = 2; k <= 2048; k <<= 1) {
        for (int j = k >> 1; j > 0; j >>= 1) {
            for (int e = tid; e < 2048; e += 256) {
                int ix = e ^ j;
                if (ix > e) {
                    u64 a = cand[e], b = cand[ix];
                    bool up = ((e & k) == 0);
                    if (up ? (a < b) : (a > b)) { cand[e] = b; cand[ix] = a; }
                }
            }
            __syncthreads();
        }
    }
    if (tid < 128) cslot[tid] = 65535 - (int)(cand[tid] & 0xFFFFull);
    __syncthreads();

    // exact fp32 rescore of 128 candidates (true top-64 provably inside:
    // fp16 approx sigma ~1.6e-5 vs top64->128 margin ~1.9e-3)
    {
        int w = tid >> 5, l = tid & 31;
        for (int j = 0; j < 16; j++) {
            int ci = w * 16 + j;
            int slot = cslot[ci];
            const float* mrow = &Mm[(size_t)slot * DIM];
            float p = 0.f;
#pragma unroll
            for (int i = 0; i < 8; i++) p = fmaf(Erow[l + 32 * i], mrow[l + 32 * i], p);
#pragma unroll
            for (int o = 16; o > 0; o >>= 1) p += __shfl_xor_sync(0xffffffffu, p, o);
            if (l == 0) tmax[ci] = mk_key(p, slot);
        }
    }
    if (tid >= 128) tmax[tid] = 0ull;
    __syncthreads();

    for (int k = 2; k <= 256; k <<= 1) {
        for (int j = k >> 1; j > 0; j >>= 1) {
            int ix = tid ^ j;
            if (ix > tid) {
                u64 a = tmax[tid], b = tmax[ix];
                bool up = ((tid & k) == 0);
                if (up ? (a < b) : (a > b)) { tmax[tid] = b; tmax[ix] = a; }
            }
            __syncthreads();
        }
    }
    if (tid < 64) Kset[t * 64 + tid] = 65535 - (int)(tmax[tid] & 0xFFFFull);
}

// ---------------- solver: 4 ADMM/mirror-descent steps per token ----------------
#define SLV_FLOATS (64 * 257 + 256 * 17 + 256 + 256 + 64 + 64 + 4 * 64 + 2 + 64)
#define SLV_BYTES  (SLV_FLOATS * 4)

__global__ __launch_bounds__(256) void k_solver(const float* __restrict__ X,
                                                const float* __restrict__ M,
                                                const float* __restrict__ A,
                                                const int* __restrict__ Kidx,
                                                float* __restrict__ Yout,
                                                __half* __restrict__ Yh) {
    extern __shared__ float sm[];
    float* Mg   = sm;                 // [64][257]
    float* band = Mg + 64 * 257;      // [256][17]
    float* Ysm  = band + 256 * 17;    // [256]
    float* vsm  = Ysm + 256;          // [256]
    float* Psm  = vsm + 256;          // [64]
    float* Lsm  = Psm + 64;           // [64]
    float* gp   = Lsm + 64;           // [4][64]
    float* red  = gp + 256;           // [2]
    int*   sidx = (int*)(red + 2);    // [64]

    int tid = threadIdx.x;
    int t = blockIdx.x;
    if (tid < 64) sidx[tid] = Kidx[t * 64 + tid];
    __syncthreads();
    for (int r = 0; r < 64; r++)
        Mg[r * 257 + tid] = M[(size_t)sidx[r] * DIM + tid];
    {
        int j = tid;
#pragma unroll
        for (int o = 0; o < 17; o++) {
            int i = j - 8 + o;
            band[j * 17 + o] = (i >= 0 && i < 256) ? A[j * 256 + i] : 0.f;
        }
    }
    float xr = X[t * DIM + tid];
    if (tid < 64) Psm[tid] = 1.0f / 64.0f;
    __syncthreads();
    {
        float y0 = 0.f;
        for (int k = 0; k < 64; k++) y0 = fmaf(Psm[k], Mg[k * 257 + tid], y0);
        Ysm[tid] = y0;
    }
    float lam = 0.f;
    __syncthreads();

    for (int step = 0; step < 4; step++) {
        float ymp = 0.f;
#pragma unroll 8
        for (int k = 0; k < 64; k++) ymp = fmaf(Psm[k], Mg[k * 257 + tid], ymp);
        float yold = Ysm[tid];
        float r_ = yold - ymp;
        lam = fmaf(RHO_C, r_, lam);
        float yab = 0.f;
#pragma unroll
        for (int o = 0; o < 17; o++) {
            int i = tid - 8 + o;
            if (i >= 0 && i < 256) yab = fmaf(band[tid * 17 + o], Ysm[i], yab);
        }
        float gY = yab - xr + lam + RHO_C * r_;
        float ynew = yold - TAU_C * gY;
        __syncthreads();
        Ysm[tid] = ynew;
        vsm[tid] = RHO_C * (ynew - ymp) + lam;
        __syncthreads();
        {
            int k = tid & 63, part = tid >> 6;
            const float* vv = vsm + part * 64;
            const float* mm = Mg + k * 257 + part * 64;
            float p_ = 0.f;
#pragma unroll 8
            for (int jj = 0; jj < 64; jj++) p_ = fmaf(vv[jj], mm[jj], p_);
            gp[part * 64 + k] = p_;
        }
        __syncthreads();
        if (tid < 64) {
            float gPk = -(gp[tid] + gp[64 + tid] + gp[128 + tid] + gp[192 + tid]);
            Lsm[tid] = logf(Psm[tid] + 1e-20f) - ETA_C * gPk;
        }
        __syncthreads();
        if (tid < 32) {
            float m_ = fmaxf(Lsm[tid], Lsm[tid + 32]);
            for (int o = 16; o > 0; o >>= 1) m_ = fmaxf(m_, __shfl_xor_sync(0xffffffffu, m_, o));
            if (tid == 0) red[0] = m_;
        }
        __syncthreads();
        if (tid < 64) Psm[tid] = expf(Lsm[tid] - red[0]);
        __syncthreads();
        if (tid < 32) {
            float s_ = Psm[tid] + Psm[tid + 32];
            for (int o = 16; o > 0; o >>= 1) s_ += __shfl_xor_sync(0xffffffffu, s_, o);
            if (tid == 0) red[1] = s_;
        }
        __syncthreads();
        if (tid < 64) Psm[tid] = Psm[tid] / red[1];
        __syncthreads();
    }
    float yfin = Ysm[tid];
    Yout[t * DIM + tid] = yfin;
    Yh[t * DIM + tid] = __float2half(yfin);
}

// ---------------- launcher ----------------
extern "C" void kernel_launch(void* const* d_in, const int* in_sizes, int n_in,
                              void* d_out, int out_size) {
    const int*   tokens = (const int*)d_in[0];
    const float* tab    = (const float*)d_in[1];
    const float* M      = (const float*)d_in[2];
    const float* A      = (const float*)d_in[3];
    float* out = (float*)d_out;

    __half *pSh, *pMh, *pEh, *pYh;
    u64* pG;
    float *pE, *pX, *pY, *pB; int* pK;
    cudaGetSymbolAddress((void**)&pSh, g_Sh);
    cudaGetSymbolAddress((void**)&pMh, g_Mh);
    cudaGetSymbolAddress((void**)&pEh, g_Eh);
    cudaGetSymbolAddress((void**)&pYh, g_Yh);
    cudaGetSymbolAddress((void**)&pG, g_Gmax);
    cudaGetSymbolAddress((void**)&pE, g_E);
    cudaGetSymbolAddress((void**)&pX, g_X);
    cudaGetSymbolAddress((void**)&pY, g_Y);
    cudaGetSymbolAddress((void**)&pB, g_bsum);
    cudaGetSymbolAddress((void**)&pK, g_K);

    k_embed<<<N_TOK, 256>>>(tokens, tab, pE, pEh);
    k_colsum<<<8, 256>>>(pE, pB);
    k_cummean<<<8, 256>>>(pE, pB, pX);
    k_cvt_h<<<(KMEM * DIM / 4 + 255) / 256, 256>>>(M, pMh, KMEM * DIM / 4);

    cudaFuncSetAttribute(k_hmma<0>, cudaFuncAttributeMaxDynamicSharedMemorySize, SMEM_BYTES);
    cudaFuncSetAttribute(k_hmma<1>, cudaFuncAttributeMaxDynamicSharedMemorySize, SMEM_BYTES);

    // scores: fp16 HMMA + fused strip maxima; token-block fastest for L2 reuse of M
    dim3 gs(N_TOK / 128, KMEM / 128);
    k_hmma<0><<<gs, 256, SMEM_BYTES>>>(pEh, pMh, pSh, nullptr, pG, KMEM);

    // tau from Gmax -> collect -> exact fp32 rescore -> exact top-64
    k_topk_rescore<<<N_TOK, 256>>>(pSh, pG, pE, M, pK);

    cudaFuncSetAttribute(k_solver, cudaFuncAttributeMaxDynamicSharedMemorySize, SLV_BYTES);
    k_solver<<<N_TOK, 256, SLV_BYTES>>>(pX, M, A, pK, pY, pYh);

    // logits: single fp16 HMMA (error ~2.9e-4 << 1e-3); token-block fastest
    dim3 gl(N_TOK / 128, (VOCAB + 127) / 128);
    k_hmma<1><<<gl, 256, SMEM_BYTES>>>(pYh, pMh, nullptr, out, nullptr, VOCAB);
}

// round 17
// speedup vs baseline: 1.3067x; 1.0330x over previous
#include <cuda_runtime.h>
#include <cuda_fp16.h>
#include <cstdint>

#define N_TOK   2048
#define DIM     256
#define KMEM    65536
#define KSHORT  64
#define VOCAB   50257
#define RHO_C   1.0f
#define TAU_C   0.1f
#define ETA_C   0.1f

typedef unsigned long long u64;
typedef unsigned int u32;

// ---------------- scratch (static __device__ — no allocation) ----------------
__device__ __align__(16) __half g_Sh[(size_t)N_TOK * KMEM];   // 256 MB approx scores
__device__ __align__(16) __half g_Mh[(size_t)KMEM * DIM];     // 32 MB fp16 memory bank
__device__ __align__(16) __half g_Eh[N_TOK * DIM];
__device__ __align__(16) __half g_Yh[N_TOK * DIM];
__device__ u64   g_Gmax[(size_t)N_TOK * 512];                 // 8 MB strip maxima
__device__ float g_E[N_TOK * DIM];
__device__ float g_X[N_TOK * DIM];
__device__ float g_Y[N_TOK * DIM];
__device__ float g_bsum[8 * DIM];
__device__ int   g_K[N_TOK * KSHORT];

#define SWZ128(o) ((o) ^ (((o) >> 3) & 0x70))
// 3 pipeline stages x (A 16KB + B 16KB) = 96KB; epilogue staging (68.6KB) aliases it.
#define SMEM_BYTES 98304

// ---------------- PTX helpers (all sm_80-era, safe for compute_103) ----------
__device__ __forceinline__ u32 smem_u32(const void* p) {
    u32 a;
    asm("{ .reg .u64 t; cvta.to.shared.u64 t, %1; cvt.u32.u64 %0, t; }" : "=r"(a) : "l"(p));
    return a;
}
__device__ __forceinline__ void ldsm4(u32* r, u32 addr) {
    asm volatile("ldmatrix.sync.aligned.m8n8.x4.shared.b16 {%0,%1,%2,%3}, [%4];"
        : "=r"(r[0]), "=r"(r[1]), "=r"(r[2]), "=r"(r[3]) : "r"(addr));
}
__device__ __forceinline__ void mma_f16(float* c, const u32* a, u32 b0, u32 b1) {
    asm volatile("mma.sync.aligned.m16n8k16.row.col.f32.f16.f16.f32 "
        "{%0,%1,%2,%3}, {%4,%5,%6,%7}, {%8,%9}, {%0,%1,%2,%3};"
        : "+f"(c[0]), "+f"(c[1]), "+f"(c[2]), "+f"(c[3])
        : "r"(a[0]), "r"(a[1]), "r"(a[2]), "r"(a[3]), "r"(b0), "r"(b1));
}
__device__ __forceinline__ void cp16(u32 dst, const void* src) {
    asm volatile("cp.async.cg.shared.global [%0], [%1], 16;" :: "r"(dst), "l"(src));
}
__device__ __forceinline__ void cp_commit() { asm volatile("cp.async.commit_group;"); }
template <int N>
__device__ __forceinline__ void cp_wait() { asm volatile("cp.async.wait_group %0;" :: "n"(N)); }

__device__ __forceinline__ u32 ordf(float f) {
    u32 u = __float_as_uint(f);
    return (u & 0x80000000u) ? ~u : (u | 0x80000000u);
}
__device__ __forceinline__ u64 mk_key(float v, int idx) {
    return ((u64)ordf(v) << 32) | (u32)(65535 - idx);
}

// ---------------- embed gather (fp32 + fp16 copies) ----------------
__global__ void k_embed(const int* __restrict__ tok, const float* __restrict__ tab,
                        float* __restrict__ E, __half* __restrict__ Eh) {
    int t = blockIdx.x, c = threadIdx.x;
    float v = tab[(size_t)tok[t] * DIM + c];
    E[t * DIM + c] = v;
    Eh[t * DIM + c] = __float2half(v);
}

// ---------------- fp32 -> fp16 bulk convert ----------------
__global__ void k_cvt_h(const float* __restrict__ src, __half* __restrict__ dst, int n4) {
    int i = blockIdx.x * 256 + threadIdx.x;
    if (i < n4) {
        float4 v = ((const float4*)src)[i];
        ((__half2*)dst)[2 * i]     = __floats2half2_rn(v.x, v.y);
        ((__half2*)dst)[2 * i + 1] = __floats2half2_rn(v.z, v.w);
    }
}

// ---------------- causal cumulative mean (2-phase) ----------------
__global__ void k_colsum(const float* __restrict__ E, float* __restrict__ bs) {
    int b = blockIdx.x, j = threadIdx.x;
    float s = 0.f;
    int base = b * 256;
#pragma unroll 4
    for (int r = 0; r < 256; r++) s += E[(base + r) * DIM + j];
    bs[b * DIM + j] = s;
}

__global__ void k_cummean(const float* __restrict__ E, const float* __restrict__ bs,
                          float* __restrict__ X) {
    int b = blockIdx.x, j = threadIdx.x;
    float acc = 0.f;
    for (int p = 0; p < b; p++) acc += bs[p * DIM + j];
    int base = b * 256;
    for (int r = 0; r < 256; r++) {
        int t = base + r;
        acc += E[t * DIM + j];
        X[t * DIM + j] = acc / (float)(t + 1);
    }
}

// ---------------- fp16 HMMA GEMM, cp.async 3-stage / single-sync ----------
// C[row][col] = dot_256(A[row], B[col]); 128x128 CTA tile, K=256 (4 chunks).
// Stage s occupies [s*32KB, s*32KB+16KB)=A, [+16KB,+32KB)=B. One __syncthreads
// per chunk: warps passing the iter-i barrier finished compute i-1, freeing
// stage (i+2)%3 == (i-1)%3 for the prefetch issued right after the barrier.
// OUTF32=0: half out + per-CTA strip-max keys -> Gmax (scores).
// OUTF32=1: fp32 out, col guard (logits).
template <int OUTF32>
__global__ __launch_bounds__(256, 2) void k_hmma(
    const __half* __restrict__ A,
    const __half* __restrict__ B,
    __half* __restrict__ Sout,
    float* __restrict__ Fout,
    u64* __restrict__ Gmax,
    int ncols)
{
    extern __shared__ char smem[];
    u32 aAddr[3] = { smem_u32(smem), smem_u32(smem + 32768), smem_u32(smem + 65536) };
    u32 bAddr[3] = { aAddr[0] + 16384, aAddr[1] + 16384, aAddr[2] + 16384 };
    int tid = threadIdx.x;
    int w = tid >> 5, l = tid & 31;
    int wm = w & 3, wn = w >> 2;
    int rowBase = blockIdx.y * 128;    // token block
    int colBase = blockIdx.x * 128;    // slot/vocab block

    float acc[2][8][4];
#pragma unroll
    for (int mi = 0; mi < 2; mi++)
#pragma unroll
        for (int ni = 0; ni < 8; ni++)
#pragma unroll
            for (int q = 0; q < 4; q++) acc[mi][ni][q] = 0.f;

    int a_row = wm * 32 + (l & 7) + ((l >> 3) & 1) * 8;   // + mi*16
    int a_kb  = ((l >> 4) * 8) * 2;                        // + ks*32
    int b_row = wn * 64 + (l & 7) + (l >> 4) * 8;          // + nj*16
    int b_kb  = (((l >> 3) & 1) * 8) * 2;                  // + ks*32

    // prologue: async-load chunks 0 and 1 into stages 0 and 1
#pragma unroll
    for (int c0 = 0; c0 < 2; c0++) {
        int kc = c0 << 6;
#pragma unroll
        for (int g = tid; g < 1024; g += 256) {
            int row = g >> 3, seg = g & 7;
            cp16(aAddr[c0] + SWZ128(row * 128 + seg * 16),
                 A + (size_t)(rowBase + row) * DIM + kc + seg * 8);
        }
#pragma unroll
        for (int g = tid; g < 1024; g += 256) {
            int row = g >> 3, seg = g & 7;
            cp16(bAddr[c0] + SWZ128(row * 128 + seg * 16),
                 B + (size_t)(colBase + row) * DIM + kc + seg * 8);
        }
        cp_commit();
    }

#pragma unroll
    for (int i = 0; i < 4; i++) {
        if (i < 3) cp_wait<1>(); else cp_wait<0>();
        __syncthreads();
        if (i + 2 < 4) {
            int kc = (i + 2) << 6, sn = (i + 2) % 3;
#pragma unroll
            for (int g = tid; g < 1024; g += 256) {
                int row = g >> 3, seg = g & 7;
                cp16(aAddr[sn] + SWZ128(row * 128 + seg * 16),
                     A + (size_t)(rowBase + row) * DIM + kc + seg * 8);
            }
#pragma unroll
            for (int g = tid; g < 1024; g += 256) {
                int row = g >> 3, seg = g & 7;
                cp16(bAddr[sn] + SWZ128(row * 128 + seg * 16),
                     B + (size_t)(colBase + row) * DIM + kc + seg * 8);
            }
            cp_commit();
        }
        int s = i % 3;
#pragma unroll
        for (int ks = 0; ks < 4; ks++) {
            u32 a[2][4];
#pragma unroll
            for (int mi = 0; mi < 2; mi++)
                ldsm4(a[mi], aAddr[s] + SWZ128((a_row + mi * 16) * 128 + a_kb + ks * 32));
            u32 b[4][4];
#pragma unroll
            for (int nj = 0; nj < 4; nj++)
                ldsm4(b[nj], bAddr[s] + SWZ128((b_row + nj * 16) * 128 + b_kb + ks * 32));
#pragma unroll
            for (int mi = 0; mi < 2; mi++)
#pragma unroll
                for (int nj = 0; nj < 4; nj++) {
                    mma_f16(acc[mi][nj * 2],     a[mi], b[nj][0], b[nj][1]);
                    mma_f16(acc[mi][nj * 2 + 1], a[mi], b[nj][2], b[nj][3]);
                }
        }
    }

    // ---- epilogue: stage 128x132 fp32 tile in smem, then coalesced copy-out --
    float* st = (float*)smem;                 // 128*132*4 = 67584 B (aliases stages)
    u64* rowmax = (u64*)(smem + 67584);       // 128*8 = 1024 B
    __syncthreads();                          // all warps done reading stages
    if (!OUTF32 && tid < 128) rowmax[tid] = 0ull;
    __syncthreads();

#pragma unroll
    for (int mi = 0; mi < 2; mi++) {
        int rl0 = wm * 32 + mi * 16 + (l >> 2);
        u64 km0 = 0ull, km8 = 0ull;
#pragma unroll
        for (int ni = 0; ni < 8; ni++) {
            int cl = wn * 64 + ni * 8 + (l & 3) * 2;
            st[rl0 * 132 + cl]           = acc[mi][ni][0];
            st[rl0 * 132 + cl + 1]       = acc[mi][ni][1];
            st[(rl0 + 8) * 132 + cl]     = acc[mi][ni][2];
            st[(rl0 + 8) * 132 + cl + 1] = acc[mi][ni][3];
            if (!OUTF32) {
                // keys from half-rounded values: consistent with stored scores
                int sl = colBase + cl;
                u64 k0 = mk_key(__half2float(__float2half(acc[mi][ni][0])), sl);
                u64 k1 = mk_key(__half2float(__float2half(acc[mi][ni][1])), sl + 1);
                u64 k2 = mk_key(__half2float(__float2half(acc[mi][ni][2])), sl);
                u64 k3 = mk_key(__half2float(__float2half(acc[mi][ni][3])), sl + 1);
                if (k1 > k0) k0 = k1;
                if (k3 > k2) k2 = k3;
                if (k0 > km0) km0 = k0;
                if (k2 > km8) km8 = k2;
            }
        }
        if (!OUTF32) {
            atomicMax(&rowmax[rl0], km0);
            atomicMax(&rowmax[rl0 + 8], km8);
        }
    }
    __syncthreads();

    if (OUTF32) {
        for (int g = tid; g < 16384; g += 256) {
            int row = g >> 7, col = g & 127;
            int c = colBase + col;
            if (c < ncols)
                Fout[(size_t)(rowBase + row) * ncols + c] = st[row * 132 + col];
        }
    } else {
        for (int g = tid; g < 8192; g += 256) {
            int row = g >> 6, cp = g & 63;
            float v0 = st[row * 132 + cp * 2];
            float v1 = st[row * 132 + cp * 2 + 1];
            *(__half2*)&Sout[(size_t)(rowBase + row) * (size_t)ncols + colBase + cp * 2] =
                __floats2half2_rn(v0, v1);
        }
        if (tid < 128)
            Gmax[(size_t)(rowBase + tid) * 512 + blockIdx.x] = rowmax[tid];
    }
}

// ---------------- top-k: Gmax tau -> collect -> exact rescore -> top-64 ------
__global__ __launch_bounds__(256) void k_topk_rescore(
    const __half* __restrict__ S,
    const u64* __restrict__ Gmax,
    const float* __restrict__ E,
    const float* __restrict__ Mm,
    int* __restrict__ Kset
) {
    __shared__ u64 cand[2048];
    __shared__ u64 smax[512];
    __shared__ u64 tmax[256];
    __shared__ float Erow[256];
    __shared__ int cslot[128];
    __shared__ int cnt;
    int tid = threadIdx.x;
    int t = blockIdx.x;
    Erow[tid] = E[t * DIM + tid];
    if (tid == 0) cnt = 0;

    // tau from precomputed 512 strip maxima (each over 128 slots)
    smax[tid]       = Gmax[(size_t)t * 512 + tid];
    smax[tid + 256] = Gmax[(size_t)t * 512 + tid + 256];
    __syncthreads();
    for (int k = 2; k <= 512; k <<= 1) {
        for (int j = k >> 1; j > 0; j >>= 1) {
            for (int e = tid; e < 512; e += 256) {
                int ix = e ^ j;
                if (ix > e) {
                    u64 a = smax[e], b = smax[ix];
                    bool up = ((e & k) == 0);
                    if (up ? (a < b) : (a > b)) { smax[e] = b; smax[ix] = a; }
                }
            }
            __syncthreads();
        }
    }
    u64 tau = smax[127];   // >=128 keys >= tau -> approx top-128 is a subset
    __syncthreads();

    // collection pass: uint4 = 8 halves per load, coalesced
    {
        const uint4* row4 = (const uint4*)(S + (size_t)t * KMEM);
#pragma unroll 4
        for (int i = 0; i < 32; i++) {
            int j4 = tid + (i << 8);
            uint4 v = row4[j4];
            int base = j4 * 8;
            u32 words[4] = { v.x, v.y, v.z, v.w };
#pragma unroll
            for (int q = 0; q < 4; q++) {
                __half2 h = *(__half2*)&words[q];
                u64 k0 = mk_key(__low2float(h), base + 2 * q);
                u64 k1 = mk_key(__high2float(h), base + 2 * q + 1);
                if (k0 >= tau) { int p = atomicAdd(&cnt, 1); if (p < 2048) cand[p] = k0; }
                if (k1 >= tau) { int p = atomicAdd(&cnt, 1); if (p < 2048) cand[p] = k1; }
            }
        }
    }
    __syncthreads();
    int c = cnt; if (c > 2048) c = 2048;
    for (int e = c + tid; e < 2048; e += 256) cand[e] = 0ull;
    __syncthreads();
    for (int k = 2; k <= 2048; k <<= 1) {
        for (int j = k >> 1; j > 0; j >>= 1) {
            for (int e = tid; e < 2048; e += 256) {
                int ix = e ^ j;
                if (ix > e) {
                    u64 a = cand[e], b = cand[ix];
                    bool up = ((e & k) == 0);
                    if (up ? (a < b) : (a > b)) { cand[e] = b; cand[ix] = a; }
                }
            }
            __syncthreads();
        }
    }
    if (tid < 128) cslot[tid] = 65535 - (int)(cand[tid] & 0xFFFFull);
    __syncthreads();

    // exact fp32 rescore of 128 candidates (true top-64 provably inside:
    // fp16 approx sigma ~1.6e-5 vs top64->128 margin ~1.9e-3)
    {
        int w = tid >> 5, l = tid & 31;
        for (int j = 0; j < 16; j++) {
            int ci = w * 16 + j;
            int slot = cslot[ci];
            const float* mrow = &Mm[(size_t)slot * DIM];
            float p = 0.f;
#pragma unroll
            for (int i = 0; i < 8; i++) p = fmaf(Erow[l + 32 * i], mrow[l + 32 * i], p);
#pragma unroll
            for (int o = 16; o > 0; o >>= 1) p += __shfl_xor_sync(0xffffffffu, p, o);
            if (l == 0) tmax[ci] = mk_key(p, slot);
        }
    }
    if (tid >= 128) tmax[tid] = 0ull;
    __syncthreads();

    for (int k = 2; k <= 256; k <<= 1) {
        for (int j = k >> 1; j > 0; j >>= 1) {
            int ix = tid ^ j;
            if (ix > tid) {
                u64 a = tmax[tid], b = tmax[ix];
                bool up = ((tid & k) == 0);
                if (up ? (a < b) : (a > b)) { tmax[tid] = b; tmax[ix] = a; }
            }
            __syncthreads();
        }
    }
    if (tid < 64) Kset[t * 64 + tid] = 65535 - (int)(tmax[tid] & 0xFFFFull);
}

// ---------------- solver: 4 ADMM/mirror-descent steps per token ----------------
#define SLV_FLOATS (64 * 257 + 256 * 17 + 256 + 256 + 64 + 64 + 4 * 64 + 2 + 64)
#define SLV_BYTES  (SLV_FLOATS * 4)

__global__ __launch_bounds__(256) void k_solver(const float* __restrict__ X,
                                                const float* __restrict__ M,
                                                const float* __restrict__ A,
                                                const int* __restrict__ Kidx,
                                                float* __restrict__ Yout,
                                                __half* __restrict__ Yh) {
    extern __shared__ float sm[];
    float* Mg   = sm;                 // [64][257]
    float* band = Mg + 64 * 257;      // [256][17]
    float* Ysm  = band + 256 * 17;    // [256]
    float* vsm  = Ysm + 256;          // [256]
    float* Psm  = vsm + 256;          // [64]
    float* Lsm  = Psm + 64;           // [64]
    float* gp   = Lsm + 64;           // [4][64]
    float* red  = gp + 256;           // [2]
    int*   sidx = (int*)(red + 2);    // [64]

    int tid = threadIdx.x;
    int t = blockIdx.x;
    if (tid < 64) sidx[tid] = Kidx[t * 64 + tid];
    __syncthreads();
    for (int r = 0; r < 64; r++)
        Mg[r * 257 + tid] = M[(size_t)sidx[r] * DIM + tid];
    {
        int j = tid;
#pragma unroll
        for (int o = 0; o < 17; o++) {
            int i = j - 8 + o;
            band[j * 17 + o] = (i >= 0 && i < 256) ? A[j * 256 + i] : 0.f;
        }
    }
    float xr = X[t * DIM + tid];
    if (tid < 64) Psm[tid] = 1.0f / 64.0f;
    __syncthreads();
    {
        float y0 = 0.f;
        for (int k = 0; k < 64; k++) y0 = fmaf(Psm[k], Mg[k * 257 + tid], y0);
        Ysm[tid] = y0;
    }
    float lam = 0.f;
    __syncthreads();

    for (int step = 0; step < 4; step++) {
        float ymp = 0.f;
#pragma unroll 8
        for (int k = 0; k < 64; k++) ymp = fmaf(Psm[k], Mg[k * 257 + tid], ymp);
        float yold = Ysm[tid];
        float r_ = yold - ymp;
        lam = fmaf(RHO_C, r_, lam);
        float yab = 0.f;
#pragma unroll
        for (int o = 0; o < 17; o++) {
            int i = tid - 8 + o;
            if (i >= 0 && i < 256) yab = fmaf(band[tid * 17 + o], Ysm[i], yab);
        }
        float gY = yab - xr + lam + RHO_C * r_;
        float ynew = yold - TAU_C * gY;
        __syncthreads();
        Ysm[tid] = ynew;
        vsm[tid] = RHO_C * (ynew - ymp) + lam;
        __syncthreads();
        {
            int k = tid & 63, part = tid >> 6;
            const float* vv = vsm + part * 64;
            const float* mm = Mg + k * 257 + part * 64;
            float p_ = 0.f;
#pragma unroll 8
            for (int jj = 0; jj < 64; jj++) p_ = fmaf(vv[jj], mm[jj], p_);
            gp[part * 64 + k] = p_;
        }
        __syncthreads();
        if (tid < 64) {
            float gPk = -(gp[tid] + gp[64 + tid] + gp[128 + tid] + gp[192 + tid]);
            Lsm[tid] = logf(Psm[tid] + 1e-20f) - ETA_C * gPk;
        }
        __syncthreads();
        if (tid < 32) {
            float m_ = fmaxf(Lsm[tid], Lsm[tid + 32]);
            for (int o = 16; o > 0; o >>= 1) m_ = fmaxf(m_, __shfl_xor_sync(0xffffffffu, m_, o));
            if (tid == 0) red[0] = m_;
        }
        __syncthreads();
        if (tid < 64) Psm[tid] = expf(Lsm[tid] - red[0]);
        __syncthreads();
        if (tid < 32) {
            float s_ = Psm[tid] + Psm[tid + 32];
            for (int o = 16; o > 0; o >>= 1) s_ += __shfl_xor_sync(0xffffffffu, s_, o);
            if (tid == 0) red[1] = s_;
        }
        __syncthreads();
        if (tid < 64) Psm[tid] = Psm[tid] / red[1];
        __syncthreads();
    }
    float yfin = Ysm[tid];
    Yout[t * DIM + tid] = yfin;
    Yh[t * DIM + tid] = __float2half(yfin);
}

// ---------------- launcher ----------------
extern "C" void kernel_launch(void* const* d_in, const int* in_sizes, int n_in,
                              void* d_out, int out_size) {
    const int*   tokens = (const int*)d_in[0];
    const float* tab    = (const float*)d_in[1];
    const float* M      = (const float*)d_in[2];
    const float* A      = (const float*)d_in[3];
    float* out = (float*)d_out;

    __half *pSh, *pMh, *pEh, *pYh;
    u64* pG;
    float *pE, *pX, *pY, *pB; int* pK;
    cudaGetSymbolAddress((void**)&pSh, g_Sh);
    cudaGetSymbolAddress((void**)&pMh, g_Mh);
    cudaGetSymbolAddress((void**)&pEh, g_Eh);
    cudaGetSymbolAddress((void**)&pYh, g_Yh);
    cudaGetSymbolAddress((void**)&pG, g_Gmax);
    cudaGetSymbolAddress((void**)&pE, g_E);
    cudaGetSymbolAddress((void**)&pX, g_X);
    cudaGetSymbolAddress((void**)&pY, g_Y);
    cudaGetSymbolAddress((void**)&pB, g_bsum);
    cudaGetSymbolAddress((void**)&pK, g_K);

    k_embed<<<N_TOK, 256>>>(tokens, tab, pE, pEh);
    k_colsum<<<8, 256>>>(pE, pB);
    k_cummean<<<8, 256>>>(pE, pB, pX);
    k_cvt_h<<<(KMEM * DIM / 4 + 255) / 256, 256>>>(M, pMh, KMEM * DIM / 4);

    cudaFuncSetAttribute(k_hmma<0>, cudaFuncAttributeMaxDynamicSharedMemorySize, SMEM_BYTES);
    cudaFuncSetAttribute(k_hmma<1>, cudaFuncAttributeMaxDynamicSharedMemorySize, SMEM_BYTES);

    // scores: fp16 HMMA (3-stage pipeline) + fused strip maxima (R13 geometry)
    dim3 gs(KMEM / 128, N_TOK / 128);
    k_hmma<0><<<gs, 256, SMEM_BYTES>>>(pEh, pMh, pSh, nullptr, pG, KMEM);

    // tau from Gmax -> collect -> exact fp32 rescore -> exact top-64
    k_topk_rescore<<<N_TOK, 256>>>(pSh, pG, pE, M, pK);

    cudaFuncSetAttribute(k_solver, cudaFuncAttributeMaxDynamicSharedMemorySize, SLV_BYTES);
    k_solver<<<N_TOK, 256, SLV_BYTES>>>(pX, M, A, pK, pY, pYh);

    // logits: single fp16 HMMA (error ~2.9e-4 << 1e-3), staged coalesced stores
    dim3 gl((VOCAB + 127) / 128, N_TOK / 128);
    k_hmma<1><<<gl, 256, SMEM_BYTES>>>(pYh, pMh, nullptr, out, nullptr, VOCAB);
}